// round 16
// baseline (speedup 1.0000x reference)
#include <cuda_runtime.h>
#include <cuda_fp16.h>
#include <cstdint>
#include <cstddef>

// ---------------- problem constants ----------------
#define B_TOTAL   32768
#define VN        10
#define C         128
#define NB        8
#define M_ROWS    80
#define GRID_FUSED 4096
#define THREADS_FUSED 320          // 10 warps: (mtile 0..4) x (nhalf 0..1)
#define STATS_BLOCKS 1184
#define N4_TOTAL  10485760
#define CNT_INV   (1.0f / 327680.0f)
#define BN_EPS    1e-5f

// ---------------- smem layout ----------------
#define XS_STRH   136              // halfs per X/O row
#define QS_STRH   392              // halfs per qkv row
#define WS_STRH   136              // halfs per weight n-row
#define XS_OFF    0                // 80*136*2 = 21760
#define QS_OFF    21760            // 80*392*2 = 62720
#define WS_OFF    84480            // 64*136*2 = 17408
#define MK_OFF    101888           // 100*4
#define SMEM_BYTES 102288          // x2 CTAs/SM

// ---------------- device scratch ----------------
__device__ float g_part[STATS_BLOCKS * 256];
__device__ __align__(16) __half g_wqkvT[384 * 128];   // n-major, s-folded
__device__ __align__(4)  __half g_twh[384];           // t @ w_qkv (fp16)
__device__ __align__(16) __half g_woutT[128 * 128];   // n-major

// ---------------- helpers ----------------
__device__ __forceinline__ uint32_t smem_u32(const void* p) {
    uint32_t a;
    asm("{ .reg .u64 t; cvta.to.shared.u64 t, %1; cvt.u32.u64 %0, t; }" : "=r"(a) : "l"(p));
    return a;
}
// m16n8k16, fp16 accumulate (2x rate if the legacy tensor path is consumer-style)
__device__ __forceinline__ void mma16h(uint32_t* c, const uint32_t* a, uint32_t b0, uint32_t b1) {
    asm volatile(
        "mma.sync.aligned.m16n8k16.row.col.f16.f16.f16.f16 "
        "{%0,%1}, {%2,%3,%4,%5}, {%6,%7}, {%0,%1};\n"
        : "+r"(c[0]), "+r"(c[1])
        : "r"(a[0]), "r"(a[1]), "r"(a[2]), "r"(a[3]), "r"(b0), "r"(b1));
}
#define LDSM4(r, addr) \
    asm volatile("ldmatrix.sync.aligned.m8n8.x4.shared.b16 {%0,%1,%2,%3}, [%4];" \
                 : "=r"((r)[0]), "=r"((r)[1]), "=r"((r)[2]), "=r"((r)[3]) : "r"(addr))

__device__ __forceinline__ void h8_to_f(uint4 u, float* f) {
    float2 t;
    t = __half22float2(*(__half2*)&u.x); f[0] = t.x; f[1] = t.y;
    t = __half22float2(*(__half2*)&u.y); f[2] = t.x; f[3] = t.y;
    t = __half22float2(*(__half2*)&u.z); f[4] = t.x; f[5] = t.y;
    t = __half22float2(*(__half2*)&u.w); f[6] = t.x; f[7] = t.y;
}

// ================= kernel 1: BN statistics (deterministic) =================
__global__ void __launch_bounds__(256) k_stats(const float4* __restrict__ x) {
    float sx = 0.f, sy = 0.f, sz = 0.f, sw = 0.f;
    float qx = 0.f, qy = 0.f, qz = 0.f, qw = 0.f;
    const int stride = STATS_BLOCKS * 256;   // mult of 32 -> fixed channel quad
    for (int i = blockIdx.x * 256 + threadIdx.x; i < N4_TOTAL; i += stride) {
        float4 v = x[i];
        sx += v.x; sy += v.y; sz += v.z; sw += v.w;
        qx += v.x * v.x; qy += v.y * v.y; qz += v.z * v.z; qw += v.w * v.w;
    }
    __shared__ float sh[4096];
    int w = threadIdx.x >> 5, l = threadIdx.x & 31;
    sh[w * 128 + l * 4 + 0] = sx; sh[w * 128 + l * 4 + 1] = sy;
    sh[w * 128 + l * 4 + 2] = sz; sh[w * 128 + l * 4 + 3] = sw;
    sh[2048 + w * 128 + l * 4 + 0] = qx; sh[2048 + w * 128 + l * 4 + 1] = qy;
    sh[2048 + w * 128 + l * 4 + 2] = qz; sh[2048 + w * 128 + l * 4 + 3] = qw;
    __syncthreads();
    int t = threadIdx.x;
    if (t < 128) {
        float a = 0.f;
        #pragma unroll
        for (int ww = 0; ww < 8; ++ww) a += sh[ww * 128 + t];
        g_part[blockIdx.x * 256 + t] = a;
    } else if (t < 256) {
        int u = t - 128;
        float a = 0.f;
        #pragma unroll
        for (int ww = 0; ww < 8; ++ww) a += sh[2048 + ww * 128 + u];
        g_part[blockIdx.x * 256 + t] = a;
    }
}

// ================= kernel 2: fold BN into weights (fp16, n-major) =================
__global__ void __launch_bounds__(384) k_prep(
    const float* __restrict__ gamma, const float* __restrict__ beta,
    const float* __restrict__ wqkv, const float* __restrict__ wout)
{
    __shared__ float s_sum[256];
    __shared__ float s_s[128], s_t[128];
    int t = threadIdx.x;
    if (t < 256) {
        float a = 0.f;
        for (int b = 0; b < STATS_BLOCKS; ++b) a += g_part[b * 256 + t];
        s_sum[t] = a;
    }
    __syncthreads();
    if (t < 128) {
        float mean = s_sum[t] * CNT_INV;
        float var  = s_sum[128 + t] * CNT_INV - mean * mean;
        float rstd = 1.0f / sqrtf(var + BN_EPS);
        float sc = gamma[t] * rstd;
        s_s[t] = sc;
        s_t[t] = beta[t] - mean * sc;
    }
    __syncthreads();
    for (int k = 0; k < 128; ++k)
        g_wqkvT[t * 128 + k] = __float2half_rn(s_s[k] * wqkv[k * 384 + t]);
    {
        float a = 0.f;
        for (int k = 0; k < 128; ++k) a += s_t[k] * wqkv[k * 384 + t];
        g_twh[t] = __float2half_rn(a);
    }
    if (t < 128)
        for (int k = 0; k < 128; ++k)
            g_woutT[t * 128 + k] = __float2half_rn(wout[k * 128 + t]);
}

// ================= kernel 3: fused (fp16-acc HMMA + ldmatrix + prefetch) =================
__global__ void __launch_bounds__(THREADS_FUSED, 2) k_fused(
    const float* __restrict__ x, const float* __restrict__ b_out,
    const float* __restrict__ mask, float* __restrict__ out)
{
    extern __shared__ __align__(16) char smraw[];
    __half* Xs = (__half*)(smraw + XS_OFF);
    __half* Qs = (__half*)(smraw + QS_OFF);
    __half* Ws = (__half*)(smraw + WS_OFF);
    float*  Mk = (float*)(smraw + MK_OFF);
    const uint32_t sbase = smem_u32(smraw);

    const int tid = threadIdx.x;
    const int warp = tid >> 5, lane = tid & 31;
    const int g = lane >> 2, tq = lane & 3;
    const int blk = blockIdx.x;

    const int mt = warp >> 1;     // m-tile (0..4)
    const int nh = warp & 1;      // n-half of the 64-wide chunk
    const int r0 = mt * 16 + g;

    // ldmatrix lane bases (byte smem addresses)
    const int lm = lane >> 3, lr = lane & 7;
    const uint32_t a_base = sbase + XS_OFF +
        (uint32_t)(((mt * 16 + (lm & 1) * 8 + lr) * XS_STRH + (lm >> 1) * 8) * 2);
    uint32_t b_base[2];
    #pragma unroll
    for (int ntp = 0; ntp < 2; ++ntp)
        b_base[ntp] = sbase + WS_OFF +
            (uint32_t)(((nh * 32 + ntp * 16 + (lm >> 1) * 8 + lr) * WS_STRH + (lm & 1) * 8) * 2);

    // ---- P0: stage X tile (fp16) + wqkv chunk0 + mask ----
    const float4* xg = (const float4*)(x + (size_t)blk * (NB * VN * C));
    #pragma unroll
    for (int it = 0; it < 8; ++it) {
        int idx = tid + it * THREADS_FUSED;      // 0..2559 (80 rows x 32 f4)
        int row = idx >> 5, c4 = idx & 31;
        float4 v = xg[idx];
        __half* dst = &Xs[row * XS_STRH + c4 * 4];
        *(__half2*)(dst + 0) = __floats2half2_rn(v.x, v.y);
        *(__half2*)(dst + 2) = __floats2half2_rn(v.z, v.w);
    }
    for (int u = tid; u < 1024; u += THREADS_FUSED) {
        int n = u >> 4, q = u & 15;
        ((uint4*)(Ws + n * WS_STRH))[q] = ((const uint4*)g_wqkvT)[u];
    }
    if (tid < 100) Mk[tid] = mask[tid];
    __syncthreads();

    // ---- preload A fragments via ldmatrix (8 x K16) ----
    uint32_t a[8][4];
    #pragma unroll
    for (int kk = 0; kk < 8; ++kk) LDSM4(a[kk], a_base + kk * 32);

    // ---- P1: qkv in 6 N-chunks of 64, register-prefetched weights ----
    for (int ch = 0; ch < 6; ++ch) {
        uint4 pf[4];
        const bool doPf = (ch < 5) && (tid < 256);
        if (doPf) {
            const uint4* wsrc = (const uint4*)(g_wqkvT + (ch + 1) * 64 * 128);
            #pragma unroll
            for (int j = 0; j < 4; ++j) pf[j] = wsrc[j * 256 + tid];
        }
        uint32_t acc[4][2];
        #pragma unroll
        for (int nt = 0; nt < 4; ++nt) { acc[nt][0] = 0u; acc[nt][1] = 0u; }
        #pragma unroll
        for (int kk = 0; kk < 8; ++kk) {
            #pragma unroll
            for (int ntp = 0; ntp < 2; ++ntp) {
                uint32_t bb[4];
                LDSM4(bb, b_base[ntp] + kk * 32);
                mma16h(acc[ntp * 2 + 0], a[kk], bb[0], bb[1]);
                mma16h(acc[ntp * 2 + 1], a[kk], bb[2], bb[3]);
            }
        }
        #pragma unroll
        for (int nt = 0; nt < 4; ++nt) {
            int col = ch * 64 + nh * 32 + nt * 8 + 2 * tq;
            __half2 tw = *(const __half2*)&g_twh[col];
            *(__half2*)&Qs[r0 * QS_STRH + col] =
                __hadd2(*(__half2*)&acc[nt][0], tw);
            *(__half2*)&Qs[(r0 + 8) * QS_STRH + col] =
                __hadd2(*(__half2*)&acc[nt][1], tw);
        }
        __syncthreads();
        if (ch < 5) {
            if (doPf) {
                #pragma unroll
                for (int j = 0; j < 4; ++j) {
                    int u = j * 256 + tid;
                    int n = u >> 4, q = u & 15;
                    ((uint4*)(Ws + n * WS_STRH))[q] = pf[j];
                }
            }
            __syncthreads();
        }
    }

    // ---- stage wout chunk0 into Ws (overlaps with softmax warps) ----
    if (tid < 256) {
        uint4 pf0[4];
        #pragma unroll
        for (int j = 0; j < 4; ++j) pf0[j] = ((const uint4*)g_woutT)[j * 256 + tid];
        #pragma unroll
        for (int j = 0; j < 4; ++j) {
            int u = j * 256 + tid;
            int n = u >> 4, q = u & 15;
            ((uint4*)(Ws + n * WS_STRH))[q] = pf0[j];
        }
    }

    // ---- P2: per-(batch,head) masked softmax; HFMA2 dots; O -> Xs fp16 ----
    {
        const int half = lane >> 4;
        const int i = lane & 15;
        const bool rowok = (i < VN);
        #pragma unroll
        for (int it = 0; it < 4; ++it) {
            int p = it * 20 + warp * 2 + half;
            bool act = (p < 64);
            int b = act ? (p >> 3) : 0;
            int h = act ? (p & 7) : 0;
            const __half* qbase = &Qs[(b * VN) * QS_STRH + h * 16];

            uint4 qv0, qv1;
            {
                const uint4* qr = (const uint4*)(qbase + (rowok ? i : 0) * QS_STRH);
                qv0 = qr[0]; qv1 = qr[1];
            }
            const __half2* qh0 = (const __half2*)&qv0;
            const __half2* qh1 = (const __half2*)&qv1;
            float mrow[VN];
            #pragma unroll
            for (int j = 0; j < VN; ++j)
                mrow[j] = Mk[(rowok ? i : 0) * VN + j] * 0.25f;

            float e[VN];
            float ssum = 0.f;
            #pragma unroll
            for (int j = 0; j < VN; ++j) {
                const uint4* kr = (const uint4*)(qbase + j * QS_STRH + 128);
                uint4 kv0 = kr[0], kv1 = kr[1];
                const __half2* kh0 = (const __half2*)&kv0;
                const __half2* kh1 = (const __half2*)&kv1;
                __half2 s = __hmul2(qh0[0], kh0[0]);
                s = __hfma2(qh0[1], kh0[1], s);
                s = __hfma2(qh0[2], kh0[2], s);
                s = __hfma2(qh0[3], kh0[3], s);
                s = __hfma2(qh1[0], kh1[0], s);
                s = __hfma2(qh1[1], kh1[1], s);
                s = __hfma2(qh1[2], kh1[2], s);
                s = __hfma2(qh1[3], kh1[3], s);
                float2 f = __half22float2(s);
                e[j] = __expf((f.x + f.y) * mrow[j]);
                ssum += e[j];
            }
            float o[16];
            #pragma unroll
            for (int d = 0; d < 16; ++d) o[d] = 0.f;
            #pragma unroll
            for (int j = 0; j < VN; ++j) {
                const uint4* vr = (const uint4*)(qbase + j * QS_STRH + 256);
                float vv[16];
                h8_to_f(vr[0], vv);
                h8_to_f(vr[1], vv + 8);
                float wj = e[j];
                #pragma unroll
                for (int d = 0; d < 16; ++d) o[d] += wj * vv[d];
            }
            if (act && rowok) {
                float inv = 1.0f / ssum;
                __half2 hp[8];
                #pragma unroll
                for (int d = 0; d < 8; ++d)
                    hp[d] = __floats2half2_rn(o[2 * d] * inv, o[2 * d + 1] * inv);
                uint4* dst = (uint4*)&Xs[(b * VN + i) * XS_STRH + h * 16];
                dst[0] = *(uint4*)&hp[0];
                dst[1] = *(uint4*)&hp[4];
            }
        }
    }
    __syncthreads();   // O ready in Xs AND wout chunk0 staged

    // ---- P3: out = O @ w_out + b_out, 2 N-chunks of 64 ----
    #pragma unroll
    for (int kk = 0; kk < 8; ++kk) LDSM4(a[kk], a_base + kk * 32);

    for (int ch = 0; ch < 2; ++ch) {
        uint4 pf[4];
        const bool doPf = (ch == 0) && (tid < 256);
        if (doPf) {
            const uint4* wsrc = (const uint4*)(g_woutT + 64 * 128);
            #pragma unroll
            for (int j = 0; j < 4; ++j) pf[j] = wsrc[j * 256 + tid];
        }
        uint32_t acc[4][2];
        #pragma unroll
        for (int nt = 0; nt < 4; ++nt) { acc[nt][0] = 0u; acc[nt][1] = 0u; }
        #pragma unroll
        for (int kk = 0; kk < 8; ++kk) {
            #pragma unroll
            for (int ntp = 0; ntp < 2; ++ntp) {
                uint32_t bb[4];
                LDSM4(bb, b_base[ntp] + kk * 32);
                mma16h(acc[ntp * 2 + 0], a[kk], bb[0], bb[1]);
                mma16h(acc[ntp * 2 + 1], a[kk], bb[2], bb[3]);
            }
        }
        #pragma unroll
        for (int nt = 0; nt < 4; ++nt) {
            int col = ch * 64 + nh * 32 + nt * 8 + 2 * tq;
            float b0v = b_out[col], b1v = b_out[col + 1];
            float2 lo = __half22float2(*(__half2*)&acc[nt][0]);
            float2 hi = __half22float2(*(__half2*)&acc[nt][1]);
            size_t ro = ((size_t)blk * M_ROWS + r0) * C + col;
            *(float2*)&out[ro] = make_float2(lo.x + b0v, lo.y + b1v);
            *(float2*)&out[ro + 8 * C] = make_float2(hi.x + b0v, hi.y + b1v);
        }
        if (ch == 0) {
            __syncthreads();
            if (doPf) {
                #pragma unroll
                for (int j = 0; j < 4; ++j) {
                    int u = j * 256 + tid;
                    int n = u >> 4, q = u & 15;
                    ((uint4*)(Ws + n * WS_STRH))[q] = pf[j];
                }
            }
            __syncthreads();
        }
    }
}

// ================= launch =================
extern "C" void kernel_launch(void* const* d_in, const int* in_sizes, int n_in,
                              void* d_out, int out_size) {
    const float* x     = (const float*)d_in[0];
    const float* gamma = (const float*)d_in[1];
    const float* beta  = (const float*)d_in[2];
    const float* wqkv  = (const float*)d_in[3];
    const float* wout  = (const float*)d_in[4];
    const float* bout  = (const float*)d_in[5];
    const float* mask  = (const float*)d_in[6];

    cudaFuncSetAttribute(k_fused, cudaFuncAttributeMaxDynamicSharedMemorySize, SMEM_BYTES);

    k_stats<<<STATS_BLOCKS, 256>>>((const float4*)x);
    k_prep<<<1, 384>>>(gamma, beta, wqkv, wout);
    k_fused<<<GRID_FUSED, THREADS_FUSED, SMEM_BYTES>>>(x, bout, mask, (float*)d_out);
}